// round 7
// baseline (speedup 1.0000x reference)
#include <cuda_runtime.h>

#define N_TOK 16384      // B*S = 4*4096
#define DDIM  2048
#define NEXP  64
#define TOPK  8
#define BM    128        // tokens per block
#define BK    16         // k-tile
#define NT    (DDIM/BK)  // 128 k-tiles
#define AS_STRIDE 132    // floats per k-row (528B), keeps STS near conflict-free

typedef unsigned long long ull;

__device__ __forceinline__ ull pack2(float lo, float hi) {
    ull r;
    asm("mov.b64 %0, {%1,%2};" : "=l"(r) : "f"(lo), "f"(hi));
    return r;
}
__device__ __forceinline__ void unpack2(ull v, float& lo, float& hi) {
    asm("mov.b64 {%0,%1}, %2;" : "=f"(lo), "=f"(hi) : "l"(v));
}
__device__ __forceinline__ ull fma2(ull a, ull b, ull c) {
    ull d;
    asm("fma.rn.f32x2 %0, %1, %2, %3;" : "=l"(d) : "l"(a), "l"(b), "l"(c));
    return d;
}
__device__ __forceinline__ ull mul2(ull a, ull b) {
    ull d;
    asm("mul.rn.f32x2 %0, %1, %2;" : "=l"(d) : "l"(a), "l"(b));
    return d;
}
__device__ __forceinline__ ull add2(ull a, ull b) {
    ull d;
    asm("add.rn.f32x2 %0, %1, %2;" : "=l"(d) : "l"(a), "l"(b));
    return d;
}

__global__ __launch_bounds__(512, 1)
void noisyk_gate_kernel(const float* __restrict__ x,
                        const float* __restrict__ W,
                        const float* __restrict__ bias,
                        float* __restrict__ g_out,
                        float* __restrict__ idx_out,
                        float* __restrict__ sc_out)
{
    __shared__ __align__(16) union {
        struct {
            float As[2][BK][AS_STRIDE];  // x tile transposed: [k][token]
            float Bs[2][BK][NEXP];       // W tile: [k][expert]
        } t;
        float Ss[BM][NEXP + 1];          // post-sigmoid scores for top-k
    } sm;

    const int tid = threadIdx.x;
    const int tx  = tid & 7;    // expert group: experts tx*8 .. tx*8+7
    const int ty  = tid >> 3;   // token group:  tokens ty*2, ty*2+1 (0..63)
    const int tokRow = blockIdx.x * BM;

    // ---- global load mappings ----
    // A: 512 threads load BM*BK = 2048 floats -> 1 float4 each
    const int am = tid >> 2;           // token 0..127
    const int ah = (tid & 3) * 4;      // k offset 0,4,8,12
    const float* xrow = x + (size_t)(tokRow + am) * DDIM + ah;
    // B: 512 threads load BK*NEXP = 1024 floats -> 1 float2 each
    const int bk = tid >> 5;           // 0..15
    const int be = (tid & 31) * 2;     // 0..62

    // ---- prefetch + stage tile 0 ----
    float4 pa = *(const float4*)(xrow);
    float2 pb = *(const float2*)(W + (size_t)bk * NEXP + be);
    {
        float av[4] = {pa.x, pa.y, pa.z, pa.w};
        #pragma unroll
        for (int c = 0; c < 4; c++) sm.t.As[0][ah + c][am] = av[c];
        *(float2*)&sm.t.Bs[0][bk][be] = pb;
    }

    // Hierarchical accumulators [token i][expert-pair jp]:
    //   acc_t: one BK=16 tile, acc_s: 16 tiles (256 k), acc_g: grand total
    ull acc_t[2][4];
    ull acc_s[2][4];
    ull acc_g[2][4];

    float bj[8];
    #pragma unroll
    for (int j = 0; j < 8; j++) bj[j] = bias[tx * 8 + j];

    __syncthreads();

    int buf = 0;
    for (int kt = 0; kt < NT; ++kt) {
        // prefetch next tile into registers
        if (kt + 1 < NT) {
            pa = *(const float4*)(xrow + (size_t)(kt + 1) * BK);
            pb = *(const float2*)(W + (size_t)((kt + 1) * BK + bk) * NEXP + be);
        }

        // ---- compute current tile into fresh acc_t ----
        #pragma unroll
        for (int kk = 0; kk < BK; ++kk) {
            float2 a = *(const float2*)&sm.t.As[buf][kk][ty * 2];
            ulonglong2 b01 = *(const ulonglong2*)&sm.t.Bs[buf][kk][tx * 8];
            ulonglong2 b23 = *(const ulonglong2*)&sm.t.Bs[buf][kk][tx * 8 + 4];
            ull aa[2];
            aa[0] = pack2(a.x, a.x);
            aa[1] = pack2(a.y, a.y);
            ull bb[4] = {b01.x, b01.y, b23.x, b23.y};
            if (kk == 0) {
                #pragma unroll
                for (int i = 0; i < 2; i++)
                    #pragma unroll
                    for (int jp = 0; jp < 4; jp++)
                        acc_t[i][jp] = mul2(aa[i], bb[jp]);
            } else {
                #pragma unroll
                for (int i = 0; i < 2; i++)
                    #pragma unroll
                    for (int jp = 0; jp < 4; jp++)
                        acc_t[i][jp] = fma2(aa[i], bb[jp], acc_t[i][jp]);
            }
        }

        // ---- hierarchical merge: tile -> super -> grand ----
        const int m = kt & 15;
        if (m == 0) {
            #pragma unroll
            for (int i = 0; i < 2; i++)
                #pragma unroll
                for (int jp = 0; jp < 4; jp++) acc_s[i][jp] = acc_t[i][jp];
        } else {
            #pragma unroll
            for (int i = 0; i < 2; i++)
                #pragma unroll
                for (int jp = 0; jp < 4; jp++) acc_s[i][jp] = add2(acc_s[i][jp], acc_t[i][jp]);
        }
        if (m == 15) {
            if (kt == 15) {
                #pragma unroll
                for (int i = 0; i < 2; i++)
                    #pragma unroll
                    for (int jp = 0; jp < 4; jp++) acc_g[i][jp] = acc_s[i][jp];
            } else {
                #pragma unroll
                for (int i = 0; i < 2; i++)
                    #pragma unroll
                    for (int jp = 0; jp < 4; jp++) acc_g[i][jp] = add2(acc_g[i][jp], acc_s[i][jp]);
            }
        }

        // stage next tile into the other smem buffer
        if (kt + 1 < NT) {
            const int nb = buf ^ 1;
            float av[4] = {pa.x, pa.y, pa.z, pa.w};
            #pragma unroll
            for (int c = 0; c < 4; c++) sm.t.As[nb][ah + c][am] = av[c];
            *(float2*)&sm.t.Bs[nb][bk][be] = pb;
        }
        __syncthreads();
        buf ^= 1;
    }

    // ---- epilogue: bias + sigmoid (precise expf), write scores ----
    #pragma unroll
    for (int i = 0; i < 2; i++) {
        const int tl = ty * 2 + i;
        float v[8];
        #pragma unroll
        for (int jp = 0; jp < 4; jp++) unpack2(acc_g[i][jp], v[2 * jp], v[2 * jp + 1]);
        float s[8];
        #pragma unroll
        for (int j = 0; j < 8; j++) {
            float z = v[j] + bj[j];
            if (z >= 0.0f) {
                s[j] = 1.0f / (1.0f + expf(-z));
            } else {
                float e = expf(z);
                s[j] = e / (1.0f + e);
            }
        }
        #pragma unroll
        for (int j = 0; j < 8; j++) sm.Ss[tl][tx * 8 + j] = s[j];
        float4* sc = (float4*)(sc_out + (size_t)(tokRow + tl) * NEXP + tx * 8);
        sc[0] = make_float4(s[0], s[1], s[2], s[3]);
        sc[1] = make_float4(s[4], s[5], s[6], s[7]);
    }
    __syncthreads();

    // ---- top-8 per token: serial insertion, strict '>' => lowest-index-first
    //      on ties, identical to jax.lax.top_k ----
    if (tid < BM) {
        float vals[TOPK];
        int   ids[TOPK];
        #pragma unroll
        for (int j = 0; j < TOPK; j++) { vals[j] = -1e30f; ids[j] = 0; }
        for (int e = 0; e < NEXP; e++) {
            float sv = sm.Ss[tid][e];
            if (sv > vals[TOPK - 1]) {
                int p = TOPK - 1;
                while (p > 0 && sv > vals[p - 1]) {
                    vals[p] = vals[p - 1];
                    ids[p]  = ids[p - 1];
                    p--;
                }
                vals[p] = sv;
                ids[p]  = e;
            }
        }
        float sum = 0.0f;
        #pragma unroll
        for (int j = 0; j < TOPK; j++) sum += vals[j];
        const float inv = 1.0f / sum;
        const size_t base = (size_t)(tokRow + tid) * TOPK;
        #pragma unroll
        for (int j = 0; j < TOPK; j++) {
            g_out[base + j]   = vals[j] * inv;
            idx_out[base + j] = (float)ids[j];
        }
    }
}

extern "C" void kernel_launch(void* const* d_in, const int* in_sizes, int n_in,
                              void* d_out, int out_size)
{
    const float* x = (const float*)d_in[0];
    const float* W = (const float*)d_in[1];
    const float* b = (const float*)d_in[2];
    // d_in[3] is k (always 8 here)

    float* out     = (float*)d_out;
    float* g_out   = out;                                  // [16384, 8]
    float* idx_out = out + (size_t)N_TOK * TOPK;           // [16384, 8] (as float)
    float* sc_out  = out + (size_t)2 * N_TOK * TOPK;       // [16384, 64]

    noisyk_gate_kernel<<<N_TOK / BM, 512>>>(x, W, b, g_out, idx_out, sc_out);
}

// round 8
// speedup vs baseline: 1.5763x; 1.5763x over previous
#include <cuda_runtime.h>

#define N_TOK 16384
#define DDIM  2048
#define NEXP  64
#define TOPK  8
#define BM    128
#define BK    16
#define HALFK 1024
#define NTH   (HALFK/BK)   // 64 tiles per k-half
#define AS_STRIDE 132

typedef unsigned long long ull;

// shared memory carve (dynamic): As | Bs | AG ; Ss unions with As/Bs
#define AS_FLOATS (2*2*BK*AS_STRIDE)          // [h][buf][k][132] = 8448 floats
#define BS_FLOATS (2*2*BK*NEXP)               // [h][buf][k][64]  = 4096 floats
#define AS_BYTES  (AS_FLOATS*4)               // 33792
#define BS_BYTES  (BS_FLOATS*4)               // 16384
#define AG_STRIDE 33                          // ull per thread (pad)
#define AG_BYTES  (256*AG_STRIDE*8)           // 67584
#define SMEM_TOTAL (AS_BYTES + BS_BYTES + AG_BYTES)  // 117760

__device__ __forceinline__ ull pack2(float lo, float hi) {
    ull r; asm("mov.b64 %0, {%1,%2};" : "=l"(r) : "f"(lo), "f"(hi)); return r;
}
__device__ __forceinline__ void unpack2(ull v, float& lo, float& hi) {
    asm("mov.b64 {%0,%1}, %2;" : "=f"(lo), "=f"(hi) : "l"(v));
}
__device__ __forceinline__ ull fma2(ull a, ull b, ull c) {
    ull d; asm("fma.rn.f32x2 %0, %1, %2, %3;" : "=l"(d) : "l"(a), "l"(b), "l"(c)); return d;
}
__device__ __forceinline__ ull mul2(ull a, ull b) {
    ull d; asm("mul.rn.f32x2 %0, %1, %2;" : "=l"(d) : "l"(a), "l"(b)); return d;
}
__device__ __forceinline__ ull add2(ull a, ull b) {
    ull d; asm("add.rn.f32x2 %0, %1, %2;" : "=l"(d) : "l"(a), "l"(b)); return d;
}

__global__ __launch_bounds__(256, 1)
void noisyk_gate_kernel(const float* __restrict__ x,
                        const float* __restrict__ W,
                        const float* __restrict__ bias,
                        float* __restrict__ g_out,
                        float* __restrict__ idx_out,
                        float* __restrict__ sc_out)
{
    extern __shared__ __align__(16) char smraw[];
    float* As = (float*)smraw;                       // [h][buf][k][AS_STRIDE]
    float* Bs = (float*)(smraw + AS_BYTES);          // [h][buf][k][NEXP]
    ull*   AG = (ull*)(smraw + AS_BYTES + BS_BYTES); // [256][AG_STRIDE]
    float* Ss = (float*)smraw;                       // [BM][65], unions with As/Bs

    const int tid   = threadIdx.x;
    const int h     = tid >> 7;        // k-half 0/1
    const int tid_h = tid & 127;
    const int tx    = tid_h & 7;       // experts tx*8 .. +7
    const int tyh   = tid_h >> 3;      // tokens tyh*8 .. +7 (0..15)
    const int tokRow = blockIdx.x * BM;
    const int kbase0 = h * HALFK;

    #define AS_AT(hh,bb,kk,tt) As[ ((((hh)*2+(bb))*BK)+(kk))*AS_STRIDE + (tt) ]
    #define BS_AT(hh,bb,kk,ee) Bs[ ((((hh)*2+(bb))*BK)+(kk))*NEXP + (ee) ]

    // ---- staging mappings (per half: 128 threads) ----
    // A tile: 128 tokens x 16 k = 512 float4 chunks; thread does chunks tid_h + 128*j
    // chunk c: token = c>>2, koff = (c&3)*4
    // B tile: 16 x 64 = 256 float4; thread does c2 = tid_h + 128*j (j=0,1)

    float4 pa[4];
    float4 pb[2];

    // prefetch+stage tile 0 of this half
    {
        const int kb = kbase0;
        #pragma unroll
        for (int j = 0; j < 4; j++) {
            int c = tid_h + 128 * j;
            int token = c >> 2, koff = (c & 3) * 4;
            pa[j] = *(const float4*)(x + (size_t)(tokRow + token) * DDIM + kb + koff);
        }
        #pragma unroll
        for (int j = 0; j < 2; j++) {
            int c2 = tid_h + 128 * j;
            int bk = c2 >> 4, be = (c2 & 15) * 4;
            pb[j] = *(const float4*)(W + (size_t)(kb + bk) * NEXP + be);
        }
        #pragma unroll
        for (int j = 0; j < 4; j++) {
            int c = tid_h + 128 * j;
            int token = c >> 2, koff = (c & 3) * 4;
            float av[4] = {pa[j].x, pa[j].y, pa[j].z, pa[j].w};
            #pragma unroll
            for (int f = 0; f < 4; f++) AS_AT(h, 0, koff + f, token) = av[f];
        }
        #pragma unroll
        for (int j = 0; j < 2; j++) {
            int c2 = tid_h + 128 * j;
            int bk = c2 >> 4, be = (c2 & 15) * 4;
            *(float4*)&BS_AT(h, 0, bk, be) = pb[j];
        }
    }

    // accumulators: [token i 0..7][expert-pair jp 0..3] -> idx i*4+jp
    ull acc_t[32];
    ull acc_s[32];

    float bj[8];
    #pragma unroll
    for (int j = 0; j < 8; j++) bj[j] = bias[tx * 8 + j];

    __syncthreads();

    ull* ag = &AG[(size_t)tid * AG_STRIDE];

    int buf = 0;
    for (int kt = 0; kt < NTH; ++kt) {
        // prefetch next tile
        if (kt + 1 < NTH) {
            const int kb = kbase0 + (kt + 1) * BK;
            #pragma unroll
            for (int j = 0; j < 4; j++) {
                int c = tid_h + 128 * j;
                int token = c >> 2, koff = (c & 3) * 4;
                pa[j] = *(const float4*)(x + (size_t)(tokRow + token) * DDIM + kb + koff);
            }
            #pragma unroll
            for (int j = 0; j < 2; j++) {
                int c2 = tid_h + 128 * j;
                int bk = c2 >> 4, be = (c2 & 15) * 4;
                pb[j] = *(const float4*)(W + (size_t)(kb + bk) * NEXP + be);
            }
        }

        // ---- compute current tile ----
        #pragma unroll
        for (int kk = 0; kk < BK; ++kk) {
            float4 a0 = *(const float4*)&AS_AT(h, buf, kk, tyh * 8);
            float4 a1 = *(const float4*)&AS_AT(h, buf, kk, tyh * 8 + 4);
            ulonglong2 b01 = *(const ulonglong2*)&BS_AT(h, buf, kk, tx * 8);
            ulonglong2 b23 = *(const ulonglong2*)&BS_AT(h, buf, kk, tx * 8 + 4);
            ull bb[4] = {b01.x, b01.y, b23.x, b23.y};
            float af[8] = {a0.x, a0.y, a0.z, a0.w, a1.x, a1.y, a1.z, a1.w};
            ull aa[8];
            #pragma unroll
            for (int i = 0; i < 8; i++) aa[i] = pack2(af[i], af[i]);
            if (kk == 0) {
                #pragma unroll
                for (int i = 0; i < 8; i++)
                    #pragma unroll
                    for (int jp = 0; jp < 4; jp++)
                        acc_t[i * 4 + jp] = mul2(aa[i], bb[jp]);
            } else {
                #pragma unroll
                for (int i = 0; i < 8; i++)
                    #pragma unroll
                    for (int jp = 0; jp < 4; jp++)
                        acc_t[i * 4 + jp] = fma2(aa[i], bb[jp], acc_t[i * 4 + jp]);
            }
        }

        // ---- hierarchical merge: tile -> super(16 tiles) -> grand(smem) ----
        const int m = kt & 15;
        if (m == 0) {
            #pragma unroll
            for (int q = 0; q < 32; q++) acc_s[q] = acc_t[q];
        } else {
            #pragma unroll
            for (int q = 0; q < 32; q++) acc_s[q] = add2(acc_s[q], acc_t[q]);
        }
        if (m == 15) {
            if (kt == 15) {
                #pragma unroll
                for (int q = 0; q < 32; q++) ag[q] = acc_s[q];
            } else {
                #pragma unroll
                for (int q = 0; q < 32; q++) ag[q] = add2(ag[q], acc_s[q]);
            }
        }

        // stage next tile into other buffer
        if (kt + 1 < NTH) {
            const int nb = buf ^ 1;
            #pragma unroll
            for (int j = 0; j < 4; j++) {
                int c = tid_h + 128 * j;
                int token = c >> 2, koff = (c & 3) * 4;
                float av[4] = {pa[j].x, pa[j].y, pa[j].z, pa[j].w};
                #pragma unroll
                for (int f = 0; f < 4; f++) AS_AT(h, nb, koff + f, token) = av[f];
            }
            #pragma unroll
            for (int j = 0; j < 2; j++) {
                int c2 = tid_h + 128 * j;
                int bk = c2 >> 4, be = (c2 & 15) * 4;
                *(float4*)&BS_AT(h, nb, bk, be) = pb[j];
            }
        }
        __syncthreads();
        buf ^= 1;
    }

    __syncthreads();   // all AG writes visible

    // ---- merge k-halves, epilogue (threads 0..127 only) ----
    if (tid < 128) {
        const ull* agp = &AG[(size_t)(tid + 128) * AG_STRIDE];
        ull tot[32];
        #pragma unroll
        for (int q = 0; q < 32; q++) tot[q] = add2(ag[q], agp[q]);

        #pragma unroll
        for (int i = 0; i < 8; i++) {
            const int tl = tyh * 8 + i;
            float v[8];
            #pragma unroll
            for (int jp = 0; jp < 4; jp++) unpack2(tot[i * 4 + jp], v[2 * jp], v[2 * jp + 1]);
            float s[8];
            #pragma unroll
            for (int j = 0; j < 8; j++) {
                float z = v[j] + bj[j];
                if (z >= 0.0f) {
                    s[j] = 1.0f / (1.0f + expf(-z));
                } else {
                    float e = expf(z);
                    s[j] = e / (1.0f + e);
                }
            }
            #pragma unroll
            for (int j = 0; j < 8; j++) Ss[tl * 65 + tx * 8 + j] = s[j];
            float4* sc = (float4*)(sc_out + (size_t)(tokRow + tl) * NEXP + tx * 8);
            sc[0] = make_float4(s[0], s[1], s[2], s[3]);
            sc[1] = make_float4(s[4], s[5], s[6], s[7]);
        }
    }
    __syncthreads();

    // ---- top-8 per token: serial insertion, strict '>' (lowest index wins ties) ----
    if (tid < BM) {
        float vals[TOPK];
        int   ids[TOPK];
        #pragma unroll
        for (int j = 0; j < TOPK; j++) { vals[j] = -1e30f; ids[j] = 0; }
        for (int e = 0; e < NEXP; e++) {
            float sv = Ss[tid * 65 + e];
            if (sv > vals[TOPK - 1]) {
                int p = TOPK - 1;
                while (p > 0 && sv > vals[p - 1]) {
                    vals[p] = vals[p - 1];
                    ids[p]  = ids[p - 1];
                    p--;
                }
                vals[p] = sv;
                ids[p]  = e;
            }
        }
        float sum = 0.0f;
        #pragma unroll
        for (int j = 0; j < TOPK; j++) sum += vals[j];
        const float inv = 1.0f / sum;
        const size_t base = (size_t)(tokRow + tid) * TOPK;
        #pragma unroll
        for (int j = 0; j < TOPK; j++) {
            g_out[base + j]   = vals[j] * inv;
            idx_out[base + j] = (float)ids[j];
        }
    }
}

extern "C" void kernel_launch(void* const* d_in, const int* in_sizes, int n_in,
                              void* d_out, int out_size)
{
    const float* x = (const float*)d_in[0];
    const float* W = (const float*)d_in[1];
    const float* b = (const float*)d_in[2];

    float* out     = (float*)d_out;
    float* g_out   = out;
    float* idx_out = out + (size_t)N_TOK * TOPK;
    float* sc_out  = out + (size_t)2 * N_TOK * TOPK;

    cudaFuncSetAttribute(noisyk_gate_kernel,
                         cudaFuncAttributeMaxDynamicSharedMemorySize, SMEM_TOTAL);
    noisyk_gate_kernel<<<N_TOK / BM, 256, SMEM_TOTAL>>>(x, W, b, g_out, idx_out, sc_out);
}